// round 9
// baseline (speedup 1.0000x reference)
#include <cuda_runtime.h>
#include <math.h>

#define IN_SIZE  256
#define N_NODES  512
#define OUT_SIZE 64
#define TT       2048
#define DD       832
#define FAN_IN   32
#define GD       768
#define MAXE     (N_NODES * FAN_IN)
#define LOG2E    1.4426950408889634f

// ---------------- device scratch ----------------
__device__ float  g_actT[GD * TT];
__device__ float  g_K[N_NODES * TT];     // K*log2e, slot 2047 zeroed
__device__ float  g_V[N_NODES * TT];
__device__ float  g_kmax[N_NODES];
__device__ float  g_kmin[N_NODES];
__device__ float  g_stat[N_NODES * 3];
__device__ float  g_immA[N_NODES * 3];
__device__ float  g_immB[N_NODES * 3];
__device__ int    g_off[N_NODES + 1];
__device__ float4 g_edge[MAXE];          // {w0, w1*log2e, w2, target-bits}

__device__ __forceinline__ float ex2f(float x) {
    float r; asm("ex2.approx.ftz.f32 %0, %1;" : "=f"(r) : "f"(x)); return r;
}

// ---------------- Phase A: tiled shifted transpose ----------------
__global__ void transpose_kernel(const float* __restrict__ actives) {
    __shared__ float tile[32][33];
    int d0 = blockIdx.x * 32;
    int t0 = blockIdx.y * 32;
    int tx = threadIdx.x, ty = threadIdx.y;        // 32 x 8
    #pragma unroll
    for (int r = 0; r < 32; r += 8) {
        int t = t0 + ty + r;
        if (t < TT - 1) tile[ty + r][tx] = actives[(t + 1) * DD + d0 + tx];
    }
    __syncthreads();
    #pragma unroll
    for (int r = 0; r < 32; r += 8) {
        int t = t0 + tx;
        if (t < TT - 1) g_actT[(d0 + ty + r) * TT + t] = tile[tx][ty + r];
    }
}

// ---------------- Phase B: K/V precompute (K scaled by log2e) ----------------
__global__ void __launch_bounds__(256) precompute_kernel(
    const float* __restrict__ weights, const int* __restrict__ in_idxs) {
    int ix  = blockIdx.x;
    int tid = threadIdx.x;
    __shared__ int   s_idx[FAN_IN];
    __shared__ float s_w1[FAN_IN], s_w2[FAN_IN];
    __shared__ float s_red[16];

    if (tid < FAN_IN) {
        s_idx[tid] = in_idxs[ix * FAN_IN + tid];
        s_w1[tid]  = weights[(ix * FAN_IN + tid) * 3 + 1] * LOG2E;
        s_w2[tid]  = weights[(ix * FAN_IN + tid) * 3 + 2];
    }
    __syncthreads();

    float kmax = -INFINITY, kmin = INFINITY;
    for (int t = tid; t < TT; t += 256) {
        if (t < TT - 1) {
            float k = 0.f, v = 0.f;
            #pragma unroll
            for (int j = 0; j < FAN_IN; j++) {
                float a = g_actT[s_idx[j] * TT + t];
                k += a * s_w1[j];
                v += a * s_w2[j];
            }
            g_K[ix * TT + t] = k;
            g_V[ix * TT + t] = v;
            kmax = fmaxf(kmax, k);
            kmin = fminf(kmin, k);
        } else {
            g_K[ix * TT + t] = 0.f;
            g_V[ix * TT + t] = 0.f;
        }
    }
    #pragma unroll
    for (int o = 16; o > 0; o >>= 1) {
        kmax = fmaxf(kmax, __shfl_xor_sync(0xFFFFFFFFu, kmax, o));
        kmin = fminf(kmin, __shfl_xor_sync(0xFFFFFFFFu, kmin, o));
    }
    int w = tid >> 5;
    if ((tid & 31) == 0) { s_red[w] = kmax; s_red[8 + w] = kmin; }
    __syncthreads();
    if (tid == 0) {
        float mx = s_red[0], mn = s_red[8];
        #pragma unroll
        for (int i = 1; i < 8; i++) { mx = fmaxf(mx, s_red[i]); mn = fminf(mn, s_red[8 + i]); }
        g_kmax[ix] = mx;
        g_kmin[ix] = mn;
    }
}

// ---------------- fused graph construction (one block, 512 threads) ----------------
__global__ void __launch_bounds__(N_NODES) graph_kernel(
    const float* __restrict__ x,
    const float* __restrict__ weights,
    const int* __restrict__ in_idxs) {
    __shared__ int s_cnt[N_NODES];
    __shared__ int s_fill[N_NODES];
    int ix = threadIdx.x;
    s_cnt[ix] = 0;
    __syncthreads();

    float s0=0,s1=0,s2=0, a0=0,a1=0,a2=0, b0=0,b1=0,b2=0;
    #pragma unroll 4
    for (int j = 0; j < FAN_IN; j++) {
        int   idx = in_idxs[ix * FAN_IN + j];
        float w0  = weights[(ix * FAN_IN + j) * 3 + 0];
        float w1  = weights[(ix * FAN_IN + j) * 3 + 1] * LOG2E;
        float w2  = weights[(ix * FAN_IN + j) * 3 + 2];
        if (idx < IN_SIZE) {
            float xv = x[idx];
            s0 += w0 * xv; s1 += w1 * xv; s2 += w2 * xv;
        } else {
            int m = idx - IN_SIZE;
            if      (m == ix - 1) { a0 += w0; a1 += w1; a2 += w2; }
            else if (m == ix - 2) { b0 += w0; b1 += w1; b2 += w2; }
            else if (m <= ix - 3) atomicAdd(&s_cnt[m], 1);
        }
    }
    g_stat[ix*3+0]=s0; g_stat[ix*3+1]=s1; g_stat[ix*3+2]=s2;
    g_immA[ix*3+0]=a0; g_immA[ix*3+1]=a1; g_immA[ix*3+2]=a2;
    g_immB[ix*3+0]=b0; g_immB[ix*3+1]=b1; g_immB[ix*3+2]=b2;
    __syncthreads();

    int v = s_cnt[ix];
    #pragma unroll
    for (int o = 1; o < N_NODES; o <<= 1) {
        int t = (ix >= o) ? s_cnt[ix - o] : 0;
        __syncthreads();
        s_cnt[ix] += t;
        __syncthreads();
    }
    int incl = s_cnt[ix];
    g_off[ix + 1] = incl;
    if (ix == 0) g_off[0] = 0;
    s_fill[ix] = incl - v;
    __syncthreads();

    #pragma unroll 4
    for (int j = 0; j < FAN_IN; j++) {
        int idx = in_idxs[ix * FAN_IN + j];
        if (idx >= IN_SIZE) {
            int m = idx - IN_SIZE;
            if (m <= ix - 3) {
                float w0 = weights[(ix * FAN_IN + j) * 3 + 0];
                float w1 = weights[(ix * FAN_IN + j) * 3 + 1] * LOG2E;
                float w2 = weights[(ix * FAN_IN + j) * 3 + 2];
                int pos = atomicAdd(&s_fill[m], 1);
                g_edge[pos] = make_float4(w0, w1, w2, __int_as_float(ix));
            }
        }
    }
}

// ---------------- Phase C: sequential scan (unroll-2, A/B register buffers) ----------------
__global__ void __launch_bounds__(256) seq_kernel(float* __restrict__ out) {
    __shared__ float  s_qa[N_NODES], s_ka[N_NODES], s_va[N_NODES];
    __shared__ float4 s_i4[N_NODES];
    __shared__ float2 s_i2[N_NODES];
    __shared__ float2 s_mm[N_NODES];
    __shared__ int    s_off[N_NODES + 1];
    __shared__ float2 s_p[2][8];

    int tid  = threadIdx.x;
    int lane = tid & 31;
    int warp = tid >> 5;

    for (int i = tid; i < N_NODES; i += 256) {
        s_qa[i] = g_stat[i*3+0];
        s_ka[i] = g_stat[i*3+1];
        s_va[i] = g_stat[i*3+2];
        s_i4[i] = make_float4(g_immA[i*3+0], g_immA[i*3+1], g_immA[i*3+2], g_immB[i*3+0]);
        s_i2[i] = make_float2(g_immB[i*3+1], g_immB[i*3+2]);
        s_mm[i] = make_float2(g_kmax[i], g_kmin[i]);
        s_off[i] = g_off[i];
    }
    if (tid == 0) s_off[N_NODES] = g_off[N_NODES];
    __syncthreads();

    // ---- A/B buffers ----
    float  kkA[8], vvA[8], kkB[8], vvB[8];
    float  qaA, kaA, vaA, qaB, kaB, vaB;
    float4 i4A, i4B;  float2 i2A, i2B, mmA, mmB;
    int    ecA = 0, eoA = 0, ecB = 0, eoB = 0;
    float4 epA = make_float4(0.f,0.f,0.f,__int_as_float(0));
    float4 epB = epA;

    // prime buffer A with node 0 (no edges: step 0 never scatters)
    qaA = s_qa[0]; kaA = s_ka[0]; vaA = s_va[0];
    i4A = s_i4[0]; i2A = s_i2[0]; mmA = s_mm[0];
    {
        float4 t0 = *(const float4*)&g_K[tid * 8];
        float4 t1 = *(const float4*)&g_K[tid * 8 + 4];
        float4 t2 = *(const float4*)&g_V[tid * 8];
        float4 t3 = *(const float4*)&g_V[tid * 8 + 4];
        kkA[0]=t0.x;kkA[1]=t0.y;kkA[2]=t0.z;kkA[3]=t0.w;
        kkA[4]=t1.x;kkA[5]=t1.y;kkA[6]=t1.z;kkA[7]=t1.w;
        vvA[0]=t2.x;vvA[1]=t2.y;vvA[2]=t2.z;vvA[3]=t2.w;
        vvA[4]=t3.x;vvA[5]=t3.y;vvA[6]=t3.z;vvA[7]=t3.w;
    }

    float out1 = 0.f, out2 = 0.f;

    #define STEP(IX, qaC,kaC,vaC,i4C,i2C,mmC,kkC,vvC,ecC,eoC,epC, \
                     qaN,kaN,vaN,i4N,i2N,mmN,kkN,vvN,ecN,eoN,epN)             \
    {                                                                          \
        int ix = (IX);                                                         \
        /* q/kl/vl from registers */                                           \
        float q    = fmaf(i4C.x, out1, fmaf(i4C.w, out2, qaC));                \
        float kl2  = fmaf(i4C.y, out1, fmaf(i2C.x, out2, kaC));                \
        float vl   = fmaf(i4C.z, out1, fmaf(i2C.y, out2, vaC));                \
        float maxl = fmaxf(fmaxf(q * mmC.x, q * mmC.y), q * kl2);              \
        /* prefetch node ix+1 into N buffers (consumed NEXT step, no copies) */\
        if (ix + 1 < N_NODES) {                                                \
            int b = ix + 1;                                                    \
            qaN = s_qa[b]; kaN = s_ka[b]; vaN = s_va[b];                       \
            i4N = s_i4[b]; i2N = s_i2[b]; mmN = s_mm[b];                       \
            float4 t0 = *(const float4*)&g_K[b * TT + tid * 8];                \
            float4 t1 = *(const float4*)&g_K[b * TT + tid * 8 + 4];            \
            float4 t2 = *(const float4*)&g_V[b * TT + tid * 8];                \
            float4 t3 = *(const float4*)&g_V[b * TT + tid * 8 + 4];            \
            kkN[0]=t0.x;kkN[1]=t0.y;kkN[2]=t0.z;kkN[3]=t0.w;                   \
            kkN[4]=t1.x;kkN[5]=t1.y;kkN[6]=t1.z;kkN[7]=t1.w;                   \
            vvN[0]=t2.x;vvN[1]=t2.y;vvN[2]=t2.z;vvN[3]=t2.w;                   \
            vvN[4]=t3.x;vvN[5]=t3.y;vvN[6]=t3.z;vvN[7]=t3.w;                   \
            eoN = s_off[ix];                       /* edges of SOURCE ix */    \
            ecN = s_off[ix + 1] - eoN;                                         \
            if (tid < ecN) epN = g_edge[eoN + tid];                            \
        }                                                                      \
        /* 8 exps/thread */                                                    \
        float se = 0.f, sev = 0.f;                                             \
        _Pragma("unroll")                                                      \
        for (int i = 0; i < 7; i++) {                                          \
            float e = ex2f(fmaf(q, kkC[i], -maxl));                            \
            se += e; sev = fmaf(e, vvC[i], sev);                               \
        }                                                                      \
        {                                                                      \
            float e7 = ex2f(fmaf(q, kkC[7], -maxl));                           \
            if (tid != 255) { se += e7; sev = fmaf(e7, vvC[7], sev); }         \
        }                                                                      \
        float tse  = ex2f(fmaf(q, kl2, -maxl));                                \
        float tsev = tse * vl;                                                 \
        /* scatter out1 via edges loaded LAST step (true full-step slack) */   \
        if (tid < ecC) {                                                       \
            int tgt = __float_as_int(epC.w);                                   \
            atomicAdd(&s_qa[tgt], epC.x * out1);                               \
            atomicAdd(&s_ka[tgt], epC.y * out1);                               \
            atomicAdd(&s_va[tgt], epC.z * out1);                               \
        }                                                                      \
        for (int e = 256 + tid; e < ecC; e += 256) {                           \
            float4 ed = g_edge[eoC + e];                                       \
            int tgt = __float_as_int(ed.w);                                    \
            atomicAdd(&s_qa[tgt], ed.x * out1);                                \
            atomicAdd(&s_ka[tgt], ed.y * out1);                                \
            atomicAdd(&s_va[tgt], ed.z * out1);                                \
        }                                                                      \
        /* warp reduction: two independent 5-level butterflies (overlapped) */ \
        _Pragma("unroll")                                                      \
        for (int o = 16; o > 0; o >>= 1) {                                     \
            se  += __shfl_xor_sync(0xFFFFFFFFu, se,  o);                       \
            sev += __shfl_xor_sync(0xFFFFFFFFu, sev, o);                       \
        }                                                                      \
        int pb = ix & 1;                                                       \
        if (lane == 0) s_p[pb][warp] = make_float2(se, sev);                   \
        __syncthreads();  /* sole bar: publishes partials + orders scatter */  \
        const float4* p4 = (const float4*)&s_p[pb][0];                         \
        float4 a0 = p4[0], a1 = p4[1], a2 = p4[2], a3 = p4[3];                 \
        float fse  = tse  + ((a0.x + a0.z) + (a1.x + a1.z))                    \
                          + ((a2.x + a2.z) + (a3.x + a3.z));                   \
        float fsev = tsev + ((a0.y + a0.w) + (a1.y + a1.w))                    \
                          + ((a2.y + a2.w) + (a3.y + a3.w));                   \
        float r  = __fdividef(fsev, fse);                                      \
        float y  = ex2f(r * (2.f * LOG2E));                                    \
        float ov = 1.f - __fdividef(2.f, y + 1.f);                             \
        out2 = out1;                                                           \
        out1 = ov;                                                             \
        if (tid == 0 && ix >= N_NODES - OUT_SIZE)                              \
            out[ix - (N_NODES - OUT_SIZE)] = ov;                               \
    }

    for (int base = 0; base < N_NODES; base += 2) {
        STEP(base,     qaA,kaA,vaA,i4A,i2A,mmA,kkA,vvA,ecA,eoA,epA,
                       qaB,kaB,vaB,i4B,i2B,mmB,kkB,vvB,ecB,eoB,epB)
        STEP(base + 1, qaB,kaB,vaB,i4B,i2B,mmB,kkB,vvB,ecB,eoB,epB,
                       qaA,kaA,vaA,i4A,i2A,mmA,kkA,vvA,ecA,eoA,epA)
    }
    #undef STEP
}

// ---------------- launch ----------------
extern "C" void kernel_launch(void* const* d_in, const int* in_sizes, int n_in,
                              void* d_out, int out_size) {
    const float* x       = (const float*)d_in[0];
    const float* actives = (const float*)d_in[1];
    const float* weights = (const float*)d_in[2];
    const int*   in_idxs = (const int*)  d_in[3];
    float* out = (float*)d_out;

    transpose_kernel<<<dim3(GD / 32, TT / 32), dim3(32, 8)>>>(actives);
    graph_kernel<<<1, N_NODES>>>(x, weights, in_idxs);
    precompute_kernel<<<N_NODES, 256>>>(weights, in_idxs);
    seq_kernel<<<1, 256>>>(out);
}

// round 13
// speedup vs baseline: 1.5930x; 1.5930x over previous
#include <cuda_runtime.h>
#include <math.h>

#define IN_SIZE  256
#define N_NODES  512
#define OUT_SIZE 64
#define TT       2048
#define DD       832
#define FAN_IN   32
#define GD       768
#define MAXE     (N_NODES * FAN_IN)
#define LOG2E    1.4426950408889634f

// ---------------- device scratch ----------------
__device__ float  g_actT[GD * TT];
__device__ float  g_K[N_NODES * TT];     // K*log2e, slot 2047 zeroed
__device__ float  g_V[N_NODES * TT];
__device__ float  g_kmax[N_NODES];
__device__ float  g_kmin[N_NODES];
__device__ float  g_stat[N_NODES * 3];
__device__ float  g_immA[N_NODES * 3];
__device__ float  g_immB[N_NODES * 3];
__device__ int    g_off[N_NODES + 1];
__device__ float4 g_edge[MAXE];          // {w0, w1*log2e, w2, target-bits}

__device__ __forceinline__ float ex2f(float x) {
    float r; asm("ex2.approx.ftz.f32 %0, %1;" : "=f"(r) : "f"(x)); return r;
}

// ---------------- Phase A: tiled shifted transpose ----------------
__global__ void transpose_kernel(const float* __restrict__ actives) {
    __shared__ float tile[32][33];
    int d0 = blockIdx.x * 32;
    int t0 = blockIdx.y * 32;
    int tx = threadIdx.x, ty = threadIdx.y;        // 32 x 8
    #pragma unroll
    for (int r = 0; r < 32; r += 8) {
        int t = t0 + ty + r;
        if (t < TT - 1) tile[ty + r][tx] = actives[(t + 1) * DD + d0 + tx];
    }
    __syncthreads();
    #pragma unroll
    for (int r = 0; r < 32; r += 8) {
        int t = t0 + tx;
        if (t < TT - 1) g_actT[(d0 + ty + r) * TT + t] = tile[tx][ty + r];
    }
}

// ---------------- Phase B: K/V precompute (K scaled by log2e) ----------------
__global__ void __launch_bounds__(256) precompute_kernel(
    const float* __restrict__ weights, const int* __restrict__ in_idxs) {
    int ix  = blockIdx.x;
    int tid = threadIdx.x;
    __shared__ int   s_idx[FAN_IN];
    __shared__ float s_w1[FAN_IN], s_w2[FAN_IN];
    __shared__ float s_red[16];

    if (tid < FAN_IN) {
        s_idx[tid] = in_idxs[ix * FAN_IN + tid];
        s_w1[tid]  = weights[(ix * FAN_IN + tid) * 3 + 1] * LOG2E;
        s_w2[tid]  = weights[(ix * FAN_IN + tid) * 3 + 2];
    }
    __syncthreads();

    float kmax = -INFINITY, kmin = INFINITY;
    for (int t = tid; t < TT; t += 256) {
        if (t < TT - 1) {
            float k = 0.f, v = 0.f;
            #pragma unroll
            for (int j = 0; j < FAN_IN; j++) {
                float a = g_actT[s_idx[j] * TT + t];
                k += a * s_w1[j];
                v += a * s_w2[j];
            }
            g_K[ix * TT + t] = k;
            g_V[ix * TT + t] = v;
            kmax = fmaxf(kmax, k);
            kmin = fminf(kmin, k);
        } else {
            g_K[ix * TT + t] = 0.f;
            g_V[ix * TT + t] = 0.f;
        }
    }
    #pragma unroll
    for (int o = 16; o > 0; o >>= 1) {
        kmax = fmaxf(kmax, __shfl_xor_sync(0xFFFFFFFFu, kmax, o));
        kmin = fminf(kmin, __shfl_xor_sync(0xFFFFFFFFu, kmin, o));
    }
    int w = tid >> 5;
    if ((tid & 31) == 0) { s_red[w] = kmax; s_red[8 + w] = kmin; }
    __syncthreads();
    if (tid == 0) {
        float mx = s_red[0], mn = s_red[8];
        #pragma unroll
        for (int i = 1; i < 8; i++) { mx = fmaxf(mx, s_red[i]); mn = fminf(mn, s_red[8 + i]); }
        g_kmax[ix] = mx;
        g_kmin[ix] = mn;
    }
}

// ---------------- fused graph construction (one block, 512 threads) ----------------
__global__ void __launch_bounds__(N_NODES) graph_kernel(
    const float* __restrict__ x,
    const float* __restrict__ weights,
    const int* __restrict__ in_idxs) {
    __shared__ int s_cnt[N_NODES];
    __shared__ int s_fill[N_NODES];
    int ix = threadIdx.x;
    s_cnt[ix] = 0;
    __syncthreads();

    float s0=0,s1=0,s2=0, a0=0,a1=0,a2=0, b0=0,b1=0,b2=0;
    #pragma unroll 4
    for (int j = 0; j < FAN_IN; j++) {
        int   idx = in_idxs[ix * FAN_IN + j];
        float w0  = weights[(ix * FAN_IN + j) * 3 + 0];
        float w1  = weights[(ix * FAN_IN + j) * 3 + 1] * LOG2E;
        float w2  = weights[(ix * FAN_IN + j) * 3 + 2];
        if (idx < IN_SIZE) {
            float xv = x[idx];
            s0 += w0 * xv; s1 += w1 * xv; s2 += w2 * xv;
        } else {
            int m = idx - IN_SIZE;
            if      (m == ix - 1) { a0 += w0; a1 += w1; a2 += w2; }
            else if (m == ix - 2) { b0 += w0; b1 += w1; b2 += w2; }
            else if (m <= ix - 3) atomicAdd(&s_cnt[m], 1);
        }
    }
    g_stat[ix*3+0]=s0; g_stat[ix*3+1]=s1; g_stat[ix*3+2]=s2;
    g_immA[ix*3+0]=a0; g_immA[ix*3+1]=a1; g_immA[ix*3+2]=a2;
    g_immB[ix*3+0]=b0; g_immB[ix*3+1]=b1; g_immB[ix*3+2]=b2;
    __syncthreads();

    int v = s_cnt[ix];
    #pragma unroll
    for (int o = 1; o < N_NODES; o <<= 1) {
        int t = (ix >= o) ? s_cnt[ix - o] : 0;
        __syncthreads();
        s_cnt[ix] += t;
        __syncthreads();
    }
    int incl = s_cnt[ix];
    g_off[ix + 1] = incl;
    if (ix == 0) g_off[0] = 0;
    s_fill[ix] = incl - v;
    __syncthreads();

    #pragma unroll 4
    for (int j = 0; j < FAN_IN; j++) {
        int idx = in_idxs[ix * FAN_IN + j];
        if (idx >= IN_SIZE) {
            int m = idx - IN_SIZE;
            if (m <= ix - 3) {
                float w0 = weights[(ix * FAN_IN + j) * 3 + 0];
                float w1 = weights[(ix * FAN_IN + j) * 3 + 1] * LOG2E;
                float w2 = weights[(ix * FAN_IN + j) * 3 + 2];
                int pos = atomicAdd(&s_fill[m], 1);
                g_edge[pos] = make_float4(w0, w1, w2, __int_as_float(ix));
            }
        }
    }
}

// ---------------- Phase C: sequential scan, 128 threads, 16 elems/thread ----------------
__global__ void __launch_bounds__(128) seq_kernel(float* __restrict__ out) {
    __shared__ float4 s_st[N_NODES];    // qa, ka, va, 0       (scatter-mutable)
    __shared__ float4 s_ia[N_NODES];    // iA0, iA1, iA2, iB0
    __shared__ float4 s_ib[N_NODES];    // iB1, iB2, kmx, kmn
    __shared__ int2   s_ec[N_NODES];    // {eoff, ecnt}
    __shared__ float2 s_p[2][4];

    int tid  = threadIdx.x;
    int lane = tid & 31;
    int warp = tid >> 5;

    for (int i = tid; i < N_NODES; i += 128) {
        s_st[i] = make_float4(g_stat[i*3+0], g_stat[i*3+1], g_stat[i*3+2], 0.f);
        s_ia[i] = make_float4(g_immA[i*3+0], g_immA[i*3+1], g_immA[i*3+2], g_immB[i*3+0]);
        s_ib[i] = make_float4(g_immB[i*3+1], g_immB[i*3+2], g_kmax[i], g_kmin[i]);
        int o0 = g_off[i], o1 = g_off[i+1];
        s_ec[i] = make_int2(o0, o1 - o0);
    }
    __syncthreads();

    // ---- prime node 0 ----
    float kk[16], vv[16];
    float4 st = s_st[0], ia = s_ia[0], ib = s_ib[0];
    {
        const float4* Kp = (const float4*)&g_K[tid * 16];
        const float4* Vp = (const float4*)&g_V[tid * 16];
        #pragma unroll
        for (int j = 0; j < 4; j++) {
            float4 a = Kp[j], c = Vp[j];
            kk[4*j]=a.x; kk[4*j+1]=a.y; kk[4*j+2]=a.z; kk[4*j+3]=a.w;
            vv[4*j]=c.x; vv[4*j+1]=c.y; vv[4*j+2]=c.z; vv[4*j+3]=c.w;
        }
    }
    int    eo = 0, ec = 0;                      // step 0 never scatters
    float4 ep = make_float4(0.f, 0.f, 0.f, __int_as_float(0));
    float  out1 = 0.f, out2 = 0.f;

    for (int ix = 0; ix < N_NODES; ix++) {
        // ---- q / kl / vl from uniform registers ----
        float q    = fmaf(ia.x, out1, fmaf(ia.w, out2, st.x));
        float kl2  = fmaf(ia.y, out1, fmaf(ib.x, out2, st.y));
        float vl   = fmaf(ia.z, out1, fmaf(ib.y, out2, st.z));
        float maxl = fmaxf(fmaxf(q * ib.z, q * ib.w), q * kl2);

        // ---- branchless prefetch of node ix+1 (last iter harmlessly reloads 0) ----
        int b = (ix + 1 < N_NODES) ? ix + 1 : 0;
        float  kn[16], vn[16];
        float4 stn = s_st[b], ian = s_ia[b], ibn = s_ib[b];
        {
            const float4* Kp = (const float4*)&g_K[b * TT + tid * 16];
            const float4* Vp = (const float4*)&g_V[b * TT + tid * 16];
            #pragma unroll
            for (int j = 0; j < 4; j++) {
                float4 a = Kp[j], c = Vp[j];
                kn[4*j]=a.x; kn[4*j+1]=a.y; kn[4*j+2]=a.z; kn[4*j+3]=a.w;
                vn[4*j]=c.x; vn[4*j+1]=c.y; vn[4*j+2]=c.z; vn[4*j+3]=c.w;
            }
        }
        int2   e2  = s_ec[ix];                 // edges of SOURCE ix (for next step)
        int    eon = e2.x, ecn = e2.y;
        float4 epn = make_float4(0.f, 0.f, 0.f, __int_as_float(0));
        if (tid < ecn) epn = g_edge[eon + tid];

        // ---- 16 exps, balanced register trees (no MIO) ----
        float e[16];
        #pragma unroll
        for (int i = 0; i < 16; i++) e[i] = ex2f(fmaf(q, kk[i], -maxl));
        if (tid == 127) e[15] = 0.f;           // padded t=2047 slot
        float f[16];
        #pragma unroll
        for (int i = 0; i < 16; i++) f[i] = e[i] * vv[i];
        float se, sev;
        {
            float s8[8], t8[8];
            #pragma unroll
            for (int i = 0; i < 8; i++) { s8[i] = e[2*i] + e[2*i+1]; t8[i] = f[2*i] + f[2*i+1]; }
            float s4a = s8[0]+s8[1], s4b = s8[2]+s8[3], s4c = s8[4]+s8[5], s4d = s8[6]+s8[7];
            float t4a = t8[0]+t8[1], t4b = t8[2]+t8[3], t4c = t8[4]+t8[5], t4d = t8[6]+t8[7];
            se  = (s4a + s4b) + (s4c + s4d);
            sev = (t4a + t4b) + (t4c + t4d);
        }
        float tse  = ex2f(fmaf(q, kl2, -maxl));   // live t=2047 term (uniform)
        float tsev = tse * vl;

        // ---- scatter out1 via edges loaded LAST step ----
        if (tid < ec) {
            int tgt = __float_as_int(ep.w);
            atomicAdd(&s_st[tgt].x, ep.x * out1);
            atomicAdd(&s_st[tgt].y, ep.y * out1);
            atomicAdd(&s_st[tgt].z, ep.z * out1);
        }
        for (int ee = 128 + tid; ee < ec; ee += 128) {   // statistically never taken
            float4 ed = g_edge[eo + ee];
            int tgt = __float_as_int(ed.w);
            atomicAdd(&s_st[tgt].x, ed.x * out1);
            atomicAdd(&s_st[tgt].y, ed.y * out1);
            atomicAdd(&s_st[tgt].z, ed.z * out1);
        }

        // ---- reduce: 2 interleaved 5-level butterflies across 32 lanes ----
        #pragma unroll
        for (int o = 16; o > 0; o >>= 1) {
            se  += __shfl_xor_sync(0xFFFFFFFFu, se,  o);
            sev += __shfl_xor_sync(0xFFFFFFFFu, sev, o);
        }
        int pb = ix & 1;
        if (lane == 0) s_p[pb][warp] = make_float2(se, sev);
        __syncthreads();   // sole bar: publishes partials + orders scatter

        const float4* p4 = (const float4*)&s_p[pb][0];
        float4 a0 = p4[0], a1 = p4[1];
        float fse  = tse  + ((a0.x + a0.z) + (a1.x + a1.z));
        float fsev = tsev + ((a0.y + a0.w) + (a1.y + a1.w));

        float r  = __fdividef(fsev, fse);
        float y  = ex2f(r * (2.f * LOG2E));
        float ov = 1.f - __fdividef(2.f, y + 1.f);   // tanh(r), robust at +/-inf
        out2 = out1;
        out1 = ov;

        if (tid == 0 && ix >= N_NODES - OUT_SIZE)
            out[ix - (N_NODES - OUT_SIZE)] = ov;

        // ---- rotate prefetched -> current (ALU pipe; loads had ~full-step slack) ----
        st = stn; ia = ian; ib = ibn;
        eo = eon; ec = ecn; ep = epn;
        #pragma unroll
        for (int i = 0; i < 16; i++) { kk[i] = kn[i]; vv[i] = vn[i]; }
    }
}

// ---------------- launch ----------------
extern "C" void kernel_launch(void* const* d_in, const int* in_sizes, int n_in,
                              void* d_out, int out_size) {
    const float* x       = (const float*)d_in[0];
    const float* actives = (const float*)d_in[1];
    const float* weights = (const float*)d_in[2];
    const int*   in_idxs = (const int*)  d_in[3];
    float* out = (float*)d_out;

    transpose_kernel<<<dim3(GD / 32, TT / 32), dim3(32, 8)>>>(actives);
    graph_kernel<<<1, N_NODES>>>(x, weights, in_idxs);
    precompute_kernel<<<N_NODES, 256>>>(weights, in_idxs);
    seq_kernel<<<1, 128>>>(out);
}

// round 14
// speedup vs baseline: 1.9450x; 1.2210x over previous
#include <cuda_runtime.h>
#include <math.h>

#define IN_SIZE  256
#define N_NODES  512
#define OUT_SIZE 64
#define TT       2048
#define DD       832
#define FAN_IN   32
#define GD       768
#define MAXE     (N_NODES * FAN_IN)
#define LOG2E    1.4426950408889634f

// ---------------- device scratch ----------------
__device__ float  g_actT[GD * TT];
__device__ float  g_K[N_NODES * TT];     // K*log2e, slot 2047 zeroed
__device__ float  g_V[N_NODES * TT];
__device__ float  g_kmax[N_NODES];       // on scaled K
__device__ float  g_kmin[N_NODES];
__device__ float4 g_w4[MAXE];            // {w0, w1*log2e, w2, idx-bits} per (node,lane)

__device__ __forceinline__ float ex2f(float x) {
    float r; asm("ex2.approx.ftz.f32 %0, %1;" : "=f"(r) : "f"(x)); return r;
}

// ---------------- Phase A: tiled shifted transpose ----------------
__global__ void transpose_kernel(const float* __restrict__ actives) {
    __shared__ float tile[32][33];
    int d0 = blockIdx.x * 32;
    int t0 = blockIdx.y * 32;
    int tx = threadIdx.x, ty = threadIdx.y;        // 32 x 8
    #pragma unroll
    for (int r = 0; r < 32; r += 8) {
        int t = t0 + ty + r;
        if (t < TT - 1) tile[ty + r][tx] = actives[(t + 1) * DD + d0 + tx];
    }
    __syncthreads();
    #pragma unroll
    for (int r = 0; r < 32; r += 8) {
        int t = t0 + tx;
        if (t < TT - 1) g_actT[(d0 + ty + r) * TT + t] = tile[tx][ty + r];
    }
}

// ---------------- packed gather table ----------------
__global__ void build_w4(const float* __restrict__ weights,
                         const int* __restrict__ in_idxs) {
    int i = blockIdx.x * blockDim.x + threadIdx.x;   // 0 .. MAXE-1
    if (i < MAXE) {
        g_w4[i] = make_float4(weights[i * 3 + 0],
                              weights[i * 3 + 1] * LOG2E,
                              weights[i * 3 + 2],
                              __int_as_float(in_idxs[i]));
    }
}

// ---------------- Phase B: K/V precompute (K scaled by log2e) ----------------
__global__ void __launch_bounds__(256) precompute_kernel(
    const float* __restrict__ weights, const int* __restrict__ in_idxs) {
    int ix  = blockIdx.x;
    int tid = threadIdx.x;
    __shared__ int   s_idx[FAN_IN];
    __shared__ float s_w1[FAN_IN], s_w2[FAN_IN];
    __shared__ float s_red[16];

    if (tid < FAN_IN) {
        s_idx[tid] = in_idxs[ix * FAN_IN + tid];
        s_w1[tid]  = weights[(ix * FAN_IN + tid) * 3 + 1] * LOG2E;
        s_w2[tid]  = weights[(ix * FAN_IN + tid) * 3 + 2];
    }
    __syncthreads();

    float kmax = -INFINITY, kmin = INFINITY;
    for (int t = tid; t < TT; t += 256) {
        if (t < TT - 1) {
            float k = 0.f, v = 0.f;
            #pragma unroll
            for (int j = 0; j < FAN_IN; j++) {
                float a = g_actT[s_idx[j] * TT + t];
                k += a * s_w1[j];
                v += a * s_w2[j];
            }
            g_K[ix * TT + t] = k;
            g_V[ix * TT + t] = v;
            kmax = fmaxf(kmax, k);
            kmin = fminf(kmin, k);
        } else {
            g_K[ix * TT + t] = 0.f;
            g_V[ix * TT + t] = 0.f;
        }
    }
    #pragma unroll
    for (int o = 16; o > 0; o >>= 1) {
        kmax = fmaxf(kmax, __shfl_xor_sync(0xFFFFFFFFu, kmax, o));
        kmin = fminf(kmin, __shfl_xor_sync(0xFFFFFFFFu, kmin, o));
    }
    int w = tid >> 5;
    if ((tid & 31) == 0) { s_red[w] = kmax; s_red[8 + w] = kmin; }
    __syncthreads();
    if (tid == 0) {
        float mx = s_red[0], mn = s_red[8];
        #pragma unroll
        for (int i = 1; i < 8; i++) { mx = fmaxf(mx, s_red[i]); mn = fminf(mn, s_red[8 + i]); }
        g_kmax[ix] = mx;
        g_kmin[ix] = mn;
    }
}

// ---------------- Phase C: sequential scan (R2 gather architecture + micro-wins) ----------------
__global__ void __launch_bounds__(256) seq_kernel(
    const float* __restrict__ x, float* __restrict__ out) {
    __shared__ float  s_row[GD];        // last row (only d<768 gathered)
    __shared__ float2 s_mm[N_NODES];    // {kmax, kmin} scaled
    __shared__ float2 s_p[2][8];        // double-buffered per-warp partials

    int tid  = threadIdx.x;
    int lane = tid & 31;
    int warp = tid >> 5;

    for (int d = tid; d < GD; d += 256)
        s_row[d] = (d < IN_SIZE) ? x[d] : 0.f;
    for (int i = tid; i < N_NODES; i += 256)
        s_mm[i] = make_float2(g_kmax[i], g_kmin[i]);
    __syncthreads();

    // ---- prime node 0 ----
    float4 w4 = g_w4[lane];                       // {w0, w1s, w2, idx}
    float2 mm = s_mm[0];
    float4 k0 = *(const float4*)&g_K[tid * 8];
    float4 k1 = *(const float4*)&g_K[tid * 8 + 4];
    float4 v0 = *(const float4*)&g_V[tid * 8];
    float4 v1 = *(const float4*)&g_V[tid * 8 + 4];

    float out1 = 0.f;

    for (int ix = 0; ix < N_NODES; ix++) {
        // ---- gather from shared last-row; patch the element written last step ----
        int   cidx = __float_as_int(w4.w);
        float a = s_row[cidx];
        if (ix > 0 && cidx == IN_SIZE + (ix - 1)) a = out1;
        if (tid == 0 && ix > 0) s_row[IN_SIZE + (ix - 1)] = out1;  // ordered by the bar below

        float p0 = a * w4.x, p1 = a * w4.y, p2 = a * w4.z;

        // snapshot current K/V before the prefetch overwrites
        float kk[8] = {k0.x,k0.y,k0.z,k0.w,k1.x,k1.y,k1.z,k1.w};
        float vv[8] = {v0.x,v0.y,v0.z,v0.w,v1.x,v1.y,v1.z,v1.w};
        float2 mmc = mm;

        // ---- prefetch node ix+1 (branchless; overlaps the butterflies) ----
        int b = (ix + 1 < N_NODES) ? ix + 1 : 0;
        w4 = g_w4[b * FAN_IN + lane];
        mm = s_mm[b];
        k0 = *(const float4*)&g_K[b * TT + tid * 8];
        k1 = *(const float4*)&g_K[b * TT + tid * 8 + 4];
        v0 = *(const float4*)&g_V[b * TT + tid * 8];
        v1 = *(const float4*)&g_V[b * TT + tid * 8 + 4];

        // ---- q / kl / vl: 3 interleaved 5-level butterflies ----
        #pragma unroll
        for (int o = 16; o > 0; o >>= 1) {
            p0 += __shfl_xor_sync(0xFFFFFFFFu, p0, o);
            p1 += __shfl_xor_sync(0xFFFFFFFFu, p1, o);
            p2 += __shfl_xor_sync(0xFFFFFFFFu, p2, o);
        }
        float q = p0, kl2 = p1, vl = p2;
        float maxl = fmaxf(fmaxf(q * mmc.x, q * mmc.y), q * kl2);   // exact softmax max

        // ---- 8 exps/thread over register K/V (bare ex2, K pre-scaled) ----
        float e[8];
        #pragma unroll
        for (int i = 0; i < 8; i++) e[i] = ex2f(fmaf(q, kk[i], -maxl));
        if (tid == 255) e[7] = 0.f;               // padded t=2047 slot
        float f[8];
        #pragma unroll
        for (int i = 0; i < 8; i++) f[i] = e[i] * vv[i];
        float se  = ((e[0]+e[1]) + (e[2]+e[3])) + ((e[4]+e[5]) + (e[6]+e[7]));
        float sev = ((f[0]+f[1]) + (f[2]+f[3])) + ((f[4]+f[5]) + (f[6]+f[7]));

        float tse  = ex2f(fmaf(q, kl2, -maxl));   // live t=2047 term
        float tsev = tse * vl;

        // ---- reduce: 2 interleaved butterflies, then cross-warp via smem ----
        #pragma unroll
        for (int o = 16; o > 0; o >>= 1) {
            se  += __shfl_xor_sync(0xFFFFFFFFu, se,  o);
            sev += __shfl_xor_sync(0xFFFFFFFFu, sev, o);
        }
        int pb = ix & 1;
        if (lane == 0) s_p[pb][warp] = make_float2(se, sev);
        __syncthreads();   // the ONLY bar per node (also orders the s_row update)

        const float4* p4 = (const float4*)&s_p[pb][0];
        float4 a0 = p4[0], a1 = p4[1], a2 = p4[2], a3 = p4[3];
        float fse  = tse  + ((a0.x + a0.z) + (a1.x + a1.z))
                          + ((a2.x + a2.z) + (a3.x + a3.z));
        float fsev = tsev + ((a0.y + a0.w) + (a1.y + a1.w))
                          + ((a2.y + a2.w) + (a3.y + a3.w));

        float r  = __fdividef(fsev, fse);
        float y  = ex2f(r * (2.f * LOG2E));
        float ov = 1.f - __fdividef(2.f, y + 1.f);   // tanh(r), robust at +/-inf
        out1 = ov;

        if (tid == 0 && ix >= N_NODES - OUT_SIZE)
            out[ix - (N_NODES - OUT_SIZE)] = ov;
    }
}

// ---------------- launch ----------------
extern "C" void kernel_launch(void* const* d_in, const int* in_sizes, int n_in,
                              void* d_out, int out_size) {
    const float* x       = (const float*)d_in[0];
    const float* actives = (const float*)d_in[1];
    const float* weights = (const float*)d_in[2];
    const int*   in_idxs = (const int*)  d_in[3];
    float* out = (float*)d_out;

    transpose_kernel<<<dim3(GD / 32, TT / 32), dim3(32, 8)>>>(actives);
    build_w4<<<(MAXE + 255) / 256, 256>>>(weights, in_idxs);
    precompute_kernel<<<N_NODES, 256>>>(weights, in_idxs);
    seq_kernel<<<1, 256>>>(x, out);
}

// round 15
// speedup vs baseline: 2.1435x; 1.1021x over previous
#include <cuda_runtime.h>
#include <math.h>

#define IN_SIZE  256
#define N_NODES  512
#define OUT_SIZE 64
#define TT       2048
#define DD       832
#define FAN_IN   32
#define GD       768
#define MAXE     (N_NODES * FAN_IN)
#define LOG2E    1.4426950408889634f

// ---------------- device scratch ----------------
__device__ float  g_actT[GD * TT];
__device__ float  g_K[N_NODES * TT];     // K*log2e, slot 2047 zeroed
__device__ float  g_V[N_NODES * TT];
__device__ float  g_kmax[N_NODES];       // on scaled K
__device__ float  g_kmin[N_NODES];
__device__ float4 g_w4[MAXE];            // {w0, w1*log2e, w2, idx-bits}
__device__ float4 g_imm[N_NODES];        // {cq, ck*log2e, cv, 0}: coeff of out_{b-1}

__device__ __forceinline__ float ex2f(float x) {
    float r; asm("ex2.approx.ftz.f32 %0, %1;" : "=f"(r) : "f"(x)); return r;
}

// ---------------- Phase A: tiled shifted transpose ----------------
__global__ void transpose_kernel(const float* __restrict__ actives) {
    __shared__ float tile[32][33];
    int d0 = blockIdx.x * 32;
    int t0 = blockIdx.y * 32;
    int tx = threadIdx.x, ty = threadIdx.y;        // 32 x 8
    #pragma unroll
    for (int r = 0; r < 32; r += 8) {
        int t = t0 + ty + r;
        if (t < TT - 1) tile[ty + r][tx] = actives[(t + 1) * DD + d0 + tx];
    }
    __syncthreads();
    #pragma unroll
    for (int r = 0; r < 32; r += 8) {
        int t = t0 + tx;
        if (t < TT - 1) g_actT[(d0 + ty + r) * TT + t] = tile[tx][ty + r];
    }
}

// ---------------- packed gather table ----------------
__global__ void build_w4(const float* __restrict__ weights,
                         const int* __restrict__ in_idxs) {
    int i = blockIdx.x * blockDim.x + threadIdx.x;   // 0 .. MAXE-1
    if (i < MAXE) {
        g_w4[i] = make_float4(weights[i * 3 + 0],
                              weights[i * 3 + 1] * LOG2E,
                              weights[i * 3 + 2],
                              __int_as_float(in_idxs[i]));
    }
}

// ---------------- immediate coefficients: imm[b] = sum_j w[b,j] * [idx==IN_SIZE+b-1] ----------------
__global__ void build_imm(const float* __restrict__ weights,
                          const int* __restrict__ in_idxs) {
    int b = blockIdx.x * blockDim.x + threadIdx.x;
    if (b >= N_NODES) return;
    float cq = 0.f, ck = 0.f, cv = 0.f;
    if (b > 0) {                                    // b=0 would alias x-entry 255
        int want = IN_SIZE + b - 1;
        #pragma unroll 4
        for (int j = 0; j < FAN_IN; j++) {
            if (in_idxs[b * FAN_IN + j] == want) {
                cq += weights[(b * FAN_IN + j) * 3 + 0];
                ck += weights[(b * FAN_IN + j) * 3 + 1] * LOG2E;
                cv += weights[(b * FAN_IN + j) * 3 + 2];
            }
        }
    }
    g_imm[b] = make_float4(cq, ck, cv, 0.f);
}

// ---------------- Phase B: K/V precompute (K scaled by log2e) ----------------
__global__ void __launch_bounds__(256) precompute_kernel(
    const float* __restrict__ weights, const int* __restrict__ in_idxs) {
    int ix  = blockIdx.x;
    int tid = threadIdx.x;
    __shared__ int   s_idx[FAN_IN];
    __shared__ float s_w1[FAN_IN], s_w2[FAN_IN];
    __shared__ float s_red[16];

    if (tid < FAN_IN) {
        s_idx[tid] = in_idxs[ix * FAN_IN + tid];
        s_w1[tid]  = weights[(ix * FAN_IN + tid) * 3 + 1] * LOG2E;
        s_w2[tid]  = weights[(ix * FAN_IN + tid) * 3 + 2];
    }
    __syncthreads();

    float kmax = -INFINITY, kmin = INFINITY;
    for (int t = tid; t < TT; t += 256) {
        if (t < TT - 1) {
            float k = 0.f, v = 0.f;
            #pragma unroll
            for (int j = 0; j < FAN_IN; j++) {
                float a = g_actT[s_idx[j] * TT + t];
                k += a * s_w1[j];
                v += a * s_w2[j];
            }
            g_K[ix * TT + t] = k;
            g_V[ix * TT + t] = v;
            kmax = fmaxf(kmax, k);
            kmin = fminf(kmin, k);
        } else {
            g_K[ix * TT + t] = 0.f;
            g_V[ix * TT + t] = 0.f;
        }
    }
    #pragma unroll
    for (int o = 16; o > 0; o >>= 1) {
        kmax = fmaxf(kmax, __shfl_xor_sync(0xFFFFFFFFu, kmax, o));
        kmin = fminf(kmin, __shfl_xor_sync(0xFFFFFFFFu, kmin, o));
    }
    int w = tid >> 5;
    if ((tid & 31) == 0) { s_red[w] = kmax; s_red[8 + w] = kmin; }
    __syncthreads();
    if (tid == 0) {
        float mx = s_red[0], mn = s_red[8];
        #pragma unroll
        for (int i = 1; i < 8; i++) { mx = fmaxf(mx, s_red[i]); mn = fminf(mn, s_red[8 + i]); }
        g_kmax[ix] = mx;
        g_kmin[ix] = mn;
    }
}

// ---------------- Phase C: sequential scan — look-ahead prep, 1-FMA critical q ----------------
__global__ void __launch_bounds__(256) seq_kernel(
    const float* __restrict__ x, float* __restrict__ out) {
    __shared__ float  s_row[GD];        // last row (only d<768 gathered); unwritten = 0
    __shared__ float4 s_im[N_NODES];    // {cq, ck_s, cv, 0}
    __shared__ float2 s_mm[N_NODES];    // {kmax, kmin} scaled
    __shared__ float2 s_p[2][8];        // double-buffered per-warp partials

    int tid  = threadIdx.x;
    int lane = tid & 31;
    int warp = tid >> 5;

    for (int d = tid; d < GD; d += 256)
        s_row[d] = (d < IN_SIZE) ? x[d] : 0.f;
    for (int i = tid; i < N_NODES; i += 256) {
        s_im[i] = g_imm[i];
        s_mm[i] = make_float2(g_kmax[i], g_kmin[i]);
    }
    __syncthreads();

    // ---- prologue: prep node 0 (row = x only; no patch, imm[0]=0) ----
    float qp, kp, vp;
    {
        float4 w0 = g_w4[lane];
        float a = s_row[__float_as_int(w0.w)];
        float p0 = a * w0.x, p1 = a * w0.y, p2 = a * w0.z;
        #pragma unroll
        for (int o = 16; o > 0; o >>= 1) {
            p0 += __shfl_xor_sync(0xFFFFFFFFu, p0, o);
            p1 += __shfl_xor_sync(0xFFFFFFFFu, p1, o);
            p2 += __shfl_xor_sync(0xFFFFFFFFu, p2, o);
        }
        qp = p0; kp = p1; vp = p2;
    }
    float4 im = s_im[0];                          // for node 0 (zero)
    float2 mm = s_mm[0];
    float4 w4 = g_w4[FAN_IN + lane];              // node 1 entries (prep at step 0)
    float4 k0 = *(const float4*)&g_K[tid * 8];
    float4 k1 = *(const float4*)&g_K[tid * 8 + 4];
    float4 v0 = *(const float4*)&g_V[tid * 8];
    float4 v1 = *(const float4*)&g_V[tid * 8 + 4];

    float out1 = 0.f;                             // out_{ix-1}

    for (int ix = 0; ix < N_NODES; ix++) {
        // ---- CRITICAL: q / kl / vl in 1 FMA each ----
        float q    = fmaf(im.x, out1, qp);
        float kl2  = fmaf(im.y, out1, kp);
        float vl   = fmaf(im.z, out1, vp);
        float maxl = fmaxf(fmaxf(q * mm.x, q * mm.y), q * kl2);

        // commit out_{ix-1} to the row (ordered for future preps by the bar below)
        if (tid == 0 && ix > 0) s_row[IN_SIZE + ix - 1] = out1;

        // snapshot current K/V before prefetch overwrites
        float kk[8] = {k0.x,k0.y,k0.z,k0.w,k1.x,k1.y,k1.z,k1.w};
        float vv[8] = {v0.x,v0.y,v0.z,v0.w,v1.x,v1.y,v1.z,v1.w};

        // ---- PREP node ix+1 (off critical path): gather row as of out_{ix-2}, patch out_{ix-1} ----
        int   cidx = __float_as_int(w4.w);
        float aP = s_row[cidx];
        if (ix >= 1 && cidx == IN_SIZE + ix - 1) aP = out1;
        float p0 = aP * w4.x, p1 = aP * w4.y, p2 = aP * w4.z;

        // ---- prefetch for next step (branchless wrap) ----
        int b  = (ix + 1 < N_NODES) ? ix + 1 : 0;
        int b2 = (ix + 2 < N_NODES) ? ix + 2 : 0;
        float4 imn = s_im[b];
        float2 mmn = s_mm[b];
        w4 = g_w4[b2 * FAN_IN + lane];            // node ix+2 entries (prep at step ix+1)
        k0 = *(const float4*)&g_K[b * TT + tid * 8];
        k1 = *(const float4*)&g_K[b * TT + tid * 8 + 4];
        v0 = *(const float4*)&g_V[b * TT + tid * 8];
        v1 = *(const float4*)&g_V[b * TT + tid * 8 + 4];

        // ---- 8 exps/thread over register K/V ----
        float e[8];
        #pragma unroll
        for (int i = 0; i < 8; i++) e[i] = ex2f(fmaf(q, kk[i], -maxl));
        if (tid == 255) e[7] = 0.f;               // padded t=2047 slot
        float f[8];
        #pragma unroll
        for (int i = 0; i < 8; i++) f[i] = e[i] * vv[i];
        float se  = ((e[0]+e[1]) + (e[2]+e[3])) + ((e[4]+e[5]) + (e[6]+e[7]));
        float sev = ((f[0]+f[1]) + (f[2]+f[3])) + ((f[4]+f[5]) + (f[6]+f[7]));

        float tse  = ex2f(fmaf(q, kl2, -maxl));   // live t=2047 term
        float tsev = tse * vl;

        // ---- 5-way interleaved butterfly: se/sev (critical) + p0/p1/p2 (prep) ----
        #pragma unroll
        for (int o = 16; o > 0; o >>= 1) {
            se  += __shfl_xor_sync(0xFFFFFFFFu, se,  o);
            sev += __shfl_xor_sync(0xFFFFFFFFu, sev, o);
            p0  += __shfl_xor_sync(0xFFFFFFFFu, p0,  o);
            p1  += __shfl_xor_sync(0xFFFFFFFFu, p1,  o);
            p2  += __shfl_xor_sync(0xFFFFFFFFu, p2,  o);
        }
        int pb = ix & 1;
        if (lane == 0) s_p[pb][warp] = make_float2(se, sev);
        __syncthreads();   // the ONLY bar (publishes partials + orders row commit)

        const float4* p4 = (const float4*)&s_p[pb][0];
        float4 a0 = p4[0], a1 = p4[1], a2 = p4[2], a3 = p4[3];
        float fse  = tse  + ((a0.x + a0.z) + (a1.x + a1.z))
                          + ((a2.x + a2.z) + (a3.x + a3.z));
        float fsev = tsev + ((a0.y + a0.w) + (a1.y + a1.w))
                          + ((a2.y + a2.w) + (a3.y + a3.w));

        float r  = __fdividef(fsev, fse);
        float y  = ex2f(r * (2.f * LOG2E));
        float ov = 1.f - __fdividef(2.f, y + 1.f);   // tanh(r), robust at +/-inf
        out1 = ov;

        if (tid == 0 && ix >= N_NODES - OUT_SIZE)
            out[ix - (N_NODES - OUT_SIZE)] = ov;

        // ---- rotate prep results + scalars (cheap scalar MOVs) ----
        qp = p0; kp = p1; vp = p2;
        im = imn; mm = mmn;
    }
}

// ---------------- launch ----------------
extern "C" void kernel_launch(void* const* d_in, const int* in_sizes, int n_in,
                              void* d_out, int out_size) {
    const float* x       = (const float*)d_in[0];
    const float* actives = (const float*)d_in[1];
    const float* weights = (const float*)d_in[2];
    const int*   in_idxs = (const int*)  d_in[3];
    float* out = (float*)d_out;

    transpose_kernel<<<dim3(GD / 32, TT / 32), dim3(32, 8)>>>(actives);
    build_w4<<<(MAXE + 255) / 256, 256>>>(weights, in_idxs);
    build_imm<<<2, 256>>>(weights, in_idxs);
    precompute_kernel<<<N_NODES, 256>>>(weights, in_idxs);
    seq_kernel<<<1, 256>>>(x, out);
}

// round 17
// speedup vs baseline: 2.1639x; 1.0095x over previous
#include <cuda_runtime.h>
#include <math.h>

#define IN_SIZE  256
#define N_NODES  512
#define OUT_SIZE 64
#define TT       2048
#define DD       832
#define FAN_IN   32
#define GD       768
#define MAXE     (N_NODES * FAN_IN)
#define LOG2E    1.4426950408889634f

// ---------------- device scratch ----------------
__device__ float  g_actT[GD * TT];
__device__ float  g_K[N_NODES * TT];     // K*log2e, slot 2047 zeroed
__device__ float  g_V[N_NODES * TT];
__device__ float  g_kmax[N_NODES];       // on scaled K
__device__ float  g_kmin[N_NODES];
__device__ float4 g_w4[MAXE];            // {w0, w1*log2e, w2, idx-bits}
__device__ float4 g_imm[N_NODES];        // {cq, ck*log2e, cv, 0}: coeff of out_{b-1}

__device__ __forceinline__ float ex2f(float x) {
    float r; asm("ex2.approx.ftz.f32 %0, %1;" : "=f"(r) : "f"(x)); return r;
}
__device__ __forceinline__ float tanhf_approx(float x) {
    float r; asm("tanh.approx.f32 %0, %1;" : "=f"(r) : "f"(x)); return r;
}

// ---------------- Phase A: tiled shifted transpose ----------------
__global__ void transpose_kernel(const float* __restrict__ actives) {
    __shared__ float tile[32][33];
    int d0 = blockIdx.x * 32;
    int t0 = blockIdx.y * 32;
    int tx = threadIdx.x, ty = threadIdx.y;        // 32 x 8
    #pragma unroll
    for (int r = 0; r < 32; r += 8) {
        int t = t0 + ty + r;
        if (t < TT - 1) tile[ty + r][tx] = actives[(t + 1) * DD + d0 + tx];
    }
    __syncthreads();
    #pragma unroll
    for (int r = 0; r < 32; r += 8) {
        int t = t0 + tx;
        if (t < TT - 1) g_actT[(d0 + ty + r) * TT + t] = tile[tx][ty + r];
    }
}

// ---------------- packed gather table ----------------
__global__ void build_w4(const float* __restrict__ weights,
                         const int* __restrict__ in_idxs) {
    int i = blockIdx.x * blockDim.x + threadIdx.x;   // 0 .. MAXE-1
    if (i < MAXE) {
        g_w4[i] = make_float4(weights[i * 3 + 0],
                              weights[i * 3 + 1] * LOG2E,
                              weights[i * 3 + 2],
                              __int_as_float(in_idxs[i]));
    }
}

// ---------------- immediate coefficients: imm[b] = sum_j w[b,j] * [idx==IN_SIZE+b-1] ----------------
__global__ void build_imm(const float* __restrict__ weights,
                          const int* __restrict__ in_idxs) {
    int b = blockIdx.x * blockDim.x + threadIdx.x;
    if (b >= N_NODES) return;
    float cq = 0.f, ck = 0.f, cv = 0.f;
    if (b > 0) {                                    // b=0 would alias x-entry 255
        int want = IN_SIZE + b - 1;
        #pragma unroll 4
        for (int j = 0; j < FAN_IN; j++) {
            if (in_idxs[b * FAN_IN + j] == want) {
                cq += weights[(b * FAN_IN + j) * 3 + 0];
                ck += weights[(b * FAN_IN + j) * 3 + 1] * LOG2E;
                cv += weights[(b * FAN_IN + j) * 3 + 2];
            }
        }
    }
    g_imm[b] = make_float4(cq, ck, cv, 0.f);
}

// ---------------- Phase B: K/V precompute (K scaled by log2e) ----------------
__global__ void __launch_bounds__(256) precompute_kernel(
    const float* __restrict__ weights, const int* __restrict__ in_idxs) {
    int ix  = blockIdx.x;
    int tid = threadIdx.x;
    __shared__ int   s_idx[FAN_IN];
    __shared__ float s_w1[FAN_IN], s_w2[FAN_IN];
    __shared__ float s_red[16];

    if (tid < FAN_IN) {
        s_idx[tid] = in_idxs[ix * FAN_IN + tid];
        s_w1[tid]  = weights[(ix * FAN_IN + tid) * 3 + 1] * LOG2E;
        s_w2[tid]  = weights[(ix * FAN_IN + tid) * 3 + 2];
    }
    __syncthreads();

    float kmax = -INFINITY, kmin = INFINITY;
    for (int t = tid; t < TT; t += 256) {
        if (t < TT - 1) {
            float k = 0.f, v = 0.f;
            #pragma unroll
            for (int j = 0; j < FAN_IN; j++) {
                float a = g_actT[s_idx[j] * TT + t];
                k += a * s_w1[j];
                v += a * s_w2[j];
            }
            g_K[ix * TT + t] = k;
            g_V[ix * TT + t] = v;
            kmax = fmaxf(kmax, k);
            kmin = fminf(kmin, k);
        } else {
            g_K[ix * TT + t] = 0.f;
            g_V[ix * TT + t] = 0.f;
        }
    }
    #pragma unroll
    for (int o = 16; o > 0; o >>= 1) {
        kmax = fmaxf(kmax, __shfl_xor_sync(0xFFFFFFFFu, kmax, o));
        kmin = fminf(kmin, __shfl_xor_sync(0xFFFFFFFFu, kmin, o));
    }
    int w = tid >> 5;
    if ((tid & 31) == 0) { s_red[w] = kmax; s_red[8 + w] = kmin; }
    __syncthreads();
    if (tid == 0) {
        float mx = s_red[0], mn = s_red[8];
        #pragma unroll
        for (int i = 1; i < 8; i++) { mx = fmaxf(mx, s_red[i]); mn = fminf(mn, s_red[8 + i]); }
        g_kmax[ix] = mx;
        g_kmin[ix] = mn;
    }
}

// ---------------- Phase C: sequential scan — 128 threads, look-ahead prep ----------------
__global__ void __launch_bounds__(128) seq_kernel(
    const float* __restrict__ x, float* __restrict__ out) {
    __shared__ float  s_row[GD];        // last row; unwritten node slots stay 0
    __shared__ float4 s_im[N_NODES];    // {cq, ck_s, cv, 0}
    __shared__ float2 s_mm[N_NODES];    // {kmax, kmin} scaled
    __shared__ float2 s_p[2][4];        // double-buffered per-warp partials

    int tid  = threadIdx.x;
    int lane = tid & 31;
    int warp = tid >> 5;

    for (int d = tid; d < GD; d += 128)
        s_row[d] = (d < IN_SIZE) ? x[d] : 0.f;
    for (int i = tid; i < N_NODES; i += 128) {
        s_im[i] = g_imm[i];
        s_mm[i] = make_float2(g_kmax[i], g_kmin[i]);
    }
    __syncthreads();

    // ---- prologue: prep node 0 (row = x only; imm[0]=0) ----
    float qp, kp, vp;
    {
        float4 w0 = g_w4[lane];
        float a = s_row[__float_as_int(w0.w)];
        float p0 = a * w0.x, p1 = a * w0.y, p2 = a * w0.z;
        #pragma unroll
        for (int o = 16; o > 0; o >>= 1) {
            p0 += __shfl_xor_sync(0xFFFFFFFFu, p0, o);
            p1 += __shfl_xor_sync(0xFFFFFFFFu, p1, o);
            p2 += __shfl_xor_sync(0xFFFFFFFFu, p2, o);
        }
        qp = p0; kp = p1; vp = p2;
    }
    float4 im = s_im[0];
    float2 mm = s_mm[0];
    float4 w4 = g_w4[FAN_IN + lane];              // node 1 entries (prep at step 0)
    float kk[16], vv[16];
    {
        const float4* Kp = (const float4*)&g_K[tid * 16];
        const float4* Vp = (const float4*)&g_V[tid * 16];
        #pragma unroll
        for (int j = 0; j < 4; j++) {
            float4 a = Kp[j], c = Vp[j];
            kk[4*j]=a.x; kk[4*j+1]=a.y; kk[4*j+2]=a.z; kk[4*j+3]=a.w;
            vv[4*j]=c.x; vv[4*j+1]=c.y; vv[4*j+2]=c.z; vv[4*j+3]=c.w;
        }
    }

    float out1 = 0.f;                             // out_{ix-1}

    for (int ix = 0; ix < N_NODES; ix++) {
        // ---- CRITICAL: q / kl / vl in 1 FMA each ----
        float q    = fmaf(im.x, out1, qp);
        float kl2  = fmaf(im.y, out1, kp);
        float vl   = fmaf(im.z, out1, vp);
        float maxl = fmaxf(fmaxf(q * mm.x, q * mm.y), q * kl2);

        // commit out_{ix-1} to the row (ordered for future preps by the bar below)
        if (tid == 0 && ix > 0) s_row[IN_SIZE + ix - 1] = out1;

        // snapshot current K/V before prefetch overwrites (ALU MOVs, off-path)
        float kc[16], vc[16];
        #pragma unroll
        for (int i = 0; i < 16; i++) { kc[i] = kk[i]; vc[i] = vv[i]; }

        // ---- PREP node ix+1 partial products (butterfly deferred to post-bar) ----
        int   cidx = __float_as_int(w4.w);
        float aP = s_row[cidx];
        if (ix >= 1 && cidx == IN_SIZE + ix - 1) aP = out1;
        float p0 = aP * w4.x, p1 = aP * w4.y, p2 = aP * w4.z;

        // ---- prefetch for next step (branchless wrap) ----
        int b  = (ix + 1 < N_NODES) ? ix + 1 : 0;
        int b2 = (ix + 2 < N_NODES) ? ix + 2 : 0;
        float4 imn = s_im[b];
        float2 mmn = s_mm[b];
        w4 = g_w4[b2 * FAN_IN + lane];            // node ix+2 entries
        {
            const float4* Kp = (const float4*)&g_K[b * TT + tid * 16];
            const float4* Vp = (const float4*)&g_V[b * TT + tid * 16];
            #pragma unroll
            for (int j = 0; j < 4; j++) {
                float4 a = Kp[j], c = Vp[j];
                kk[4*j]=a.x; kk[4*j+1]=a.y; kk[4*j+2]=a.z; kk[4*j+3]=a.w;
                vv[4*j]=c.x; vv[4*j+1]=c.y; vv[4*j+2]=c.z; vv[4*j+3]=c.w;
            }
        }

        // ---- 16 exps/thread over register K/V ----
        float e[16];
        #pragma unroll
        for (int i = 0; i < 16; i++) e[i] = ex2f(fmaf(q, kc[i], -maxl));
        if (tid == 127) e[15] = 0.f;              // padded t=2047 slot
        float f[16];
        #pragma unroll
        for (int i = 0; i < 16; i++) f[i] = e[i] * vc[i];
        float se, sev;
        {
            float s8[8], t8[8];
            #pragma unroll
            for (int i = 0; i < 8; i++) { s8[i] = e[2*i] + e[2*i+1]; t8[i] = f[2*i] + f[2*i+1]; }
            float s4a = s8[0]+s8[1], s4b = s8[2]+s8[3], s4c = s8[4]+s8[5], s4d = s8[6]+s8[7];
            float t4a = t8[0]+t8[1], t4b = t8[2]+t8[3], t4c = t8[4]+t8[5], t4d = t8[6]+t8[7];
            se  = (s4a + s4b) + (s4c + s4d);
            sev = (t4a + t4b) + (t4c + t4d);
        }
        float tse  = ex2f(fmaf(q, kl2, -maxl));   // live t=2047 term
        float tsev = tse * vl;

        // ---- critical butterfly: se/sev only (10 SHFLs pre-bar) ----
        #pragma unroll
        for (int o = 16; o > 0; o >>= 1) {
            se  += __shfl_xor_sync(0xFFFFFFFFu, se,  o);
            sev += __shfl_xor_sync(0xFFFFFFFFu, sev, o);
        }
        int pb = ix & 1;
        if (lane == 0) s_p[pb][warp] = make_float2(se, sev);
        __syncthreads();   // the ONLY bar (publishes partials + orders row commit)

        // ---- prep butterfly post-bar: hides under combine/tanh serial chain ----
        #pragma unroll
        for (int o = 16; o > 0; o >>= 1) {
            p0 += __shfl_xor_sync(0xFFFFFFFFu, p0, o);
            p1 += __shfl_xor_sync(0xFFFFFFFFu, p1, o);
            p2 += __shfl_xor_sync(0xFFFFFFFFu, p2, o);
        }

        const float4* p4 = (const float4*)&s_p[pb][0];
        float4 a0 = p4[0], a1 = p4[1];
        float fse  = tse  + ((a0.x + a0.z) + (a1.x + a1.z));
        float fsev = tsev + ((a0.y + a0.w) + (a1.y + a1.w));

        float r  = __fdividef(fsev, fse);
        float ov = tanhf_approx(r);               // single-instruction tanh
        out1 = ov;

        if (tid == 0 && ix >= N_NODES - OUT_SIZE)
            out[ix - (N_NODES - OUT_SIZE)] = ov;

        // ---- rotate prep results + scalars ----
        qp = p0; kp = p1; vp = p2;
        im = imn; mm = mmn;
    }
}

// ---------------- launch ----------------
extern "C" void kernel_launch(void* const* d_in, const int* in_sizes, int n_in,
                              void* d_out, int out_size) {
    const float* x       = (const float*)d_in[0];
    const float* actives = (const float*)d_in[1];
    const float* weights = (const float*)d_in[2];
    const int*   in_idxs = (const int*)  d_in[3];
    float* out = (float*)d_out;

    transpose_kernel<<<dim3(GD / 32, TT / 32), dim3(32, 8)>>>(actives);
    build_w4<<<(MAXE + 255) / 256, 256>>>(weights, in_idxs);
    build_imm<<<2, 256>>>(weights, in_idxs);
    precompute_kernel<<<N_NODES, 256>>>(weights, in_idxs);
    seq_kernel<<<1, 128>>>(x, out);
}